// round 8
// baseline (speedup 1.0000x reference)
#include <cuda_runtime.h>
#include <cstdint>

#define NV 4000
#define NE 16000
#define DD 64
#define NSPLIT 9
#define NKBLK 500      /* 16000 / 32 */
#define BK 32

// ---------------- device scratch ----------------
__device__ float g_x1e[NE * DD];                 // 4 MB
__device__ float g_sv[DD];
__device__ float g_se[5 * DD];
__device__ float g_x0b[DD];
__device__ int   g_ecount[5];
__device__ int   g_eidx[5 * NE];
__device__ float g_csplit[(size_t)NSPLIT * NV * DD];

// ---------------- helpers ----------------
__device__ __forceinline__ uint32_t tf32_cvt(float x) {
    uint32_t u;
    asm("cvt.rna.tf32.f32 %0, %1;" : "=r"(u) : "f"(x));
    return u;
}
__device__ __forceinline__ uint32_t s2u(const void* p) {
    return (uint32_t)__cvta_generic_to_shared(p);
}
__device__ __forceinline__ void mma_tf32(float c[4],
                                         uint32_t a0, uint32_t a1, uint32_t a2, uint32_t a3,
                                         uint32_t b0, uint32_t b1) {
    asm volatile(
        "mma.sync.aligned.m16n8k8.row.col.f32.tf32.tf32.f32 "
        "{%0,%1,%2,%3},{%4,%5,%6,%7},{%8,%9},{%0,%1,%2,%3};"
        : "+f"(c[0]), "+f"(c[1]), "+f"(c[2]), "+f"(c[3])
        : "r"(a0), "r"(a1), "r"(a2), "r"(a3), "r"(b0), "r"(b1));
}

// ---------------- kernel 0: zero scratch ----------------
__global__ void zero_kernel() {
    int t = threadIdx.x;            // 512 threads
    if (t < 64) g_sv[t] = 0.f;
    else if (t < 384) g_se[t - 64] = 0.f;
    else if (t < 389) g_ecount[t - 384] = 0;
}

// ---------------- kernel 1: bucket edges by order ----------------
__global__ void scatter_kernel(const int* __restrict__ orders) {
    int e = blockIdx.x * 256 + threadIdx.x;
    if (e < NE) {
        int o = orders[e];
        int p = atomicAdd(&g_ecount[o], 1);
        g_eidx[o * NE + p] = e;
    }
}

// ---------------- kernel 2: column-sum of x_v ----------------
__global__ void vreduce_kernel(const float* __restrict__ xv) {
    __shared__ float red[256];
    int tid = threadIdx.x;
    int j = tid & 63, rg = tid >> 6;
    int base = blockIdx.x * 128;
    float a = 0.f;
#pragma unroll 8
    for (int k = 0; k < 32; k++) {
        int r = base + 4 * k + rg;
        if (r < NV) a += xv[r * DD + j];
    }
    red[tid] = a;
    __syncthreads();
    if (tid < DD) {
        float s = red[tid] + red[tid + 64] + red[tid + 128] + red[tid + 192];
        atomicAdd(&g_sv[tid], s);
    }
}

// ---------------- kernel 3: bucketed edge matvec x1_e = x_e @ W1[ord] + colsums ----------------
#define EPASS 16
__global__ void __launch_bounds__(256)
edge2_kernel(const float* __restrict__ xe, const float* __restrict__ W) {
    __shared__ float Wsh[4096];
    __shared__ float xsh[EPASS * DD];
    __shared__ float accsh[DD];
    int tid = threadIdx.x;
    int o = blockIdx.y;             // order 0..4
    int nb = gridDim.x;
    int n = g_ecount[o];

    const float4* Wp = reinterpret_cast<const float4*>(W + (size_t)(5 + o) * 4096);
#pragma unroll
    for (int i = 0; i < 4; i++)
        reinterpret_cast<float4*>(Wsh)[tid + 256 * i] = __ldg(Wp + tid + 256 * i);
    if (tid < DD) accsh[tid] = 0.f;
    __syncthreads();

    int el = tid >> 4;              // 0..15 edge slot
    int jt = tid & 15;              // 4-col group
    for (int base = blockIdx.x * EPASS; base < n; base += nb * EPASS) {
        int cnt = min(EPASS, n - base);
        float4 xr = make_float4(0.f, 0.f, 0.f, 0.f);
        int e = -1;
        if (el < cnt) {
            e = g_eidx[o * NE + base + el];
            xr = __ldg(reinterpret_cast<const float4*>(xe + (size_t)e * DD) + jt);
        }
        reinterpret_cast<float4*>(xsh)[el * 16 + jt] = xr;
        __syncthreads();

        if (tid < DD) {
            float s = 0.f;
#pragma unroll
            for (int k = 0; k < EPASS; k++) s += xsh[k * DD + tid];
            accsh[tid] += s;
        }
        if (el < cnt) {
            float4 acc = make_float4(0.f, 0.f, 0.f, 0.f);
#pragma unroll 8
            for (int i = 0; i < DD; i++) {
                float x = xsh[el * DD + i];
                float4 w = *reinterpret_cast<const float4*>(&Wsh[i * DD + jt * 4]);
                acc.x = fmaf(x, w.x, acc.x);
                acc.y = fmaf(x, w.y, acc.y);
                acc.z = fmaf(x, w.z, acc.z);
                acc.w = fmaf(x, w.w, acc.w);
            }
            reinterpret_cast<float4*>(g_x1e)[(size_t)e * 16 + jt] = acc;
        }
        __syncthreads();
    }
    if (tid < DD) atomicAdd(&g_se[o * DD + tid], accsh[tid]);
}

// ---------------- kernel 4: x0 + b (parallel: 384 threads, 6 matvecs) ----------------
__global__ void __launch_bounds__(384)
x0_kernel(const float* __restrict__ W, const float* __restrict__ b) {
    __shared__ float part[6][DD];
    int tid = threadIdx.x;
    int mat = tid / DD;             // 0..5
    int j = tid & 63;
    const float* v = (mat == 0) ? g_sv : g_se + (mat - 1) * DD;
    const float* Wm = W + (size_t)((mat == 0) ? 1 : (mat - 1)) * 4096;   // W[0][*]
    float acc = 0.f;
#pragma unroll 16
    for (int i = 0; i < DD; i++)
        acc = fmaf(v[i], __ldg(Wm + i * DD + j), acc);
    part[mat][j] = acc;
    __syncthreads();
    if (tid < DD) {
        float s = 0.f;
#pragma unroll
        for (int m = 0; m < 6; m++) s += part[m][tid];
        g_x0b[tid] = s * (1.0f / 20000.0f) + b[tid];
    }
}

// ---------------- kernel 5: split-K tf32 GEMM, cp.async A staging ----------------
__global__ void __launch_bounds__(128)
gemm_kernel(const float* __restrict__ inc) {
    __shared__ float As[2][128 * 32];   // 32 KB, XOR-swizzled per row
    __shared__ float Bs[2][32 * 64];    // 16 KB, XOR-swizzled per row

    int tid = threadIdx.x;
    int warp = tid >> 5, lane = tid & 31;
    int g = lane >> 2, tig = lane & 3;
    int tile = blockIdx.x, split = blockIdx.y;

    int b0 = (split * NKBLK) / NSPLIT;
    int b1 = ((split + 1) * NKBLK) / NSPLIT;
    int niter = b1 - b0;
    int kbase = b0 * BK;

    // A staging: thread t owns smem row t (CTA-local)
    int arow = tile * 128 + tid;
    const float* aptr = inc + (size_t)(arow < NV ? arow : 0) * NE;
    unsigned asz = (arow < NV) ? 16u : 0u;
    uint32_t adst[2] = { s2u(&As[0][tid * 32]), s2u(&As[1][tid * 32]) };
    int axor = tid & 7;

    int brow = tid >> 4, bc4 = tid & 15;

    float Creg[2][8][4];
#pragma unroll
    for (int m = 0; m < 2; m++)
#pragma unroll
        for (int n8 = 0; n8 < 8; n8++)
#pragma unroll
            for (int c = 0; c < 4; c++) Creg[m][n8][c] = 0.f;

#define STAGE_A(buf, kb) do {                                                  \
    _Pragma("unroll")                                                          \
    for (int i = 0; i < 8; i++) {                                              \
        uint32_t d = adst[buf] + (uint32_t)(((i ^ axor) << 4));                \
        asm volatile("cp.async.ca.shared.global [%0], [%1], 16, %2;"           \
                     :: "r"(d), "l"(aptr + (kb) + i * 4), "r"(asz));           \
    }                                                                          \
    asm volatile("cp.async.commit_group;");                                    \
} while (0)

#define LDG_B(dst, kb) do {                                                    \
    _Pragma("unroll")                                                          \
    for (int cc = 0; cc < 4; cc++)                                             \
        dst[cc] = __ldg(reinterpret_cast<const float4*>(                       \
                        g_x1e + (size_t)((kb) + brow + 8 * cc) * DD) + bc4);   \
} while (0)

#define STS_B(buf, src) do {                                                   \
    _Pragma("unroll")                                                          \
    for (int cc = 0; cc < 4; cc++) {                                           \
        int br = brow + 8 * cc;                                                \
        int pc = bc4 ^ (2 * (br & 3));                                         \
        float4 v;                                                              \
        v.x = __uint_as_float(tf32_cvt(src[cc].x));                            \
        v.y = __uint_as_float(tf32_cvt(src[cc].y));                            \
        v.z = __uint_as_float(tf32_cvt(src[cc].z));                            \
        v.w = __uint_as_float(tf32_cvt(src[cc].w));                            \
        *reinterpret_cast<float4*>(&Bs[buf][br * 64 + pc * 4]) = v;            \
    }                                                                          \
} while (0)

    // ---- prologue ----
    float4 bp[4];
    STAGE_A(0, kbase);
    LDG_B(bp, kbase);
    STS_B(0, bp);
    asm volatile("cp.async.wait_group 0;");
    __syncthreads();

    int rb0 = warp * 16 + g;
    for (int it = 0; it < niter; ++it) {
        int cbuf = it & 1, nbuf = cbuf ^ 1;
        bool hasnext = (it + 1) < niter;
        if (hasnext) {
            int kb = kbase + (it + 1) * BK;
            STAGE_A(nbuf, kb);
            LDG_B(bp, kb);
        }
        const float* Ac = As[cbuf];
        const float* Bc = Bs[cbuf];
#pragma unroll
        for (int q = 0; q < 4; q++) {
            uint32_t bf0[8], bf1[8];
            int kr = q * 8 + tig;
#pragma unroll
            for (int n8 = 0; n8 < 8; n8++) {
                int pc0 = ((n8 ^ tig) << 3) + g;
                bf0[n8] = __float_as_uint(Bc[kr * 64 + pc0]);
                bf1[n8] = __float_as_uint(Bc[(kr + 4) * 64 + pc0]);
            }
#pragma unroll
            for (int m = 0; m < 2; m++) {
                int r = rb0 + m * 64;
                int c0 = (((2 * q) ^ g) << 2) + tig;
                int c1 = (((2 * q + 1) ^ g) << 2) + tig;
                uint32_t a0 = tf32_cvt(Ac[r * 32 + c0]);
                uint32_t a1 = tf32_cvt(Ac[(r + 8) * 32 + c0]);
                uint32_t a2 = tf32_cvt(Ac[r * 32 + c1]);
                uint32_t a3 = tf32_cvt(Ac[(r + 8) * 32 + c1]);
#pragma unroll
                for (int n8 = 0; n8 < 8; n8++)
                    mma_tf32(Creg[m][n8], a0, a1, a2, a3, bf0[n8], bf1[n8]);
            }
        }
        if (hasnext) {
            STS_B(nbuf, bp);
            asm volatile("cp.async.wait_group 0;");
            __syncthreads();
        }
    }

    // ---- store split partials ----
    int rowbase = tile * 128 + warp * 16;
#pragma unroll
    for (int m = 0; m < 2; m++) {
#pragma unroll
        for (int part = 0; part < 2; part++) {
            int row = rowbase + m * 64 + part * 8 + g;
            if (row < NV) {
                float* op = g_csplit + ((size_t)split * NV + row) * DD + tig * 2;
#pragma unroll
                for (int n8 = 0; n8 < 8; n8++) {
                    float2 v2 = make_float2(Creg[m][n8][part * 2],
                                            Creg[m][n8][part * 2 + 1]);
                    *reinterpret_cast<float2*>(op + n8 * 8) = v2;
                }
            }
        }
    }
}

// ---------------- kernel 6: epilogue ----------------
__global__ void __launch_bounds__(256)
epilogue_kernel(const float* __restrict__ xv,
                const float* __restrict__ sn,
                const float* __restrict__ W,
                float* __restrict__ out) {
    __shared__ float Wsh[DD * DD];
    __shared__ float xvsh[4 * DD];
    int tid = threadIdx.x;
    int r0 = blockIdx.x * 4;
    int rloc = tid >> 6, j = tid & 63;
    int row = r0 + rloc;

    const float4* W4 = reinterpret_cast<const float4*>(W + 6 * 4096);  // W[1][1]
#pragma unroll
    for (int c = 0; c < 4; c++)
        reinterpret_cast<float4*>(Wsh)[tid + 256 * c] = __ldg(W4 + tid + 256 * c);
    if (tid < 64)
        reinterpret_cast<float4*>(xvsh)[tid] =
            __ldg(reinterpret_cast<const float4*>(xv + (size_t)r0 * DD) + tid);
    __syncthreads();

    float acc = 0.f;
#pragma unroll 8
    for (int i = 0; i < DD; i++)
        acc = fmaf(xvsh[rloc * DD + i], Wsh[i * DD + j], acc);

    float csum = 0.f;
#pragma unroll
    for (int s = 0; s < NSPLIT; s++)
        csum += g_csplit[((size_t)s * NV + row) * DD + j];

    float rinv = 1.0f / (1.0f + __ldg(sn + row));
    out[(size_t)row * DD + j] = (acc + csum) * rinv + g_x0b[j];
}

// ---------------- launch ----------------
extern "C" void kernel_launch(void* const* d_in, const int* in_sizes, int n_in,
                              void* d_out, int out_size) {
    const float* x_v    = (const float*)d_in[0];
    const float* x_e    = (const float*)d_in[1];
    const float* inc    = (const float*)d_in[2];
    const int*   orders = (const int*)  d_in[3];
    const float* sn     = (const float*)d_in[4];
    const float* W      = (const float*)d_in[5];
    const float* b      = (const float*)d_in[6];
    float*       out    = (float*)d_out;

    zero_kernel    <<<1, 512>>>();
    scatter_kernel <<<(NE + 255) / 256, 256>>>(orders);
    vreduce_kernel <<<32, 256>>>(x_v);
    dim3 egrid(50, 5);
    edge2_kernel   <<<egrid, 256>>>(x_e, W);
    x0_kernel      <<<1, 384>>>(W, b);
    dim3 ggrid(32, NSPLIT);
    gemm_kernel    <<<ggrid, 128>>>(inc);
    epilogue_kernel<<<NV / 4, 256>>>(x_v, sn, W, out);
}

// round 13
// speedup vs baseline: 1.4402x; 1.4402x over previous
#include <cuda_runtime.h>
#include <cstdint>

#define NV 4000
#define NE 16000
#define DD 64
#define NSPLIT 9
#define NKBLK 500      /* 16000 / 32 */
#define BK 32

// ---------------- device scratch ----------------
__device__ float g_x1e[NE * DD];                 // 4 MB
__device__ float g_sv[DD];
__device__ float g_se[5 * DD];
__device__ float g_x0b[DD];
__device__ int   g_ecount[5];
__device__ int   g_eidx[5 * NE];
__device__ float g_csplit[(size_t)NSPLIT * NV * DD];

// ---------------- helpers ----------------
__device__ __forceinline__ uint32_t tf32_cvt(float x) {
    uint32_t u;
    asm("cvt.rna.tf32.f32 %0, %1;" : "=r"(u) : "f"(x));
    return u;
}
__device__ __forceinline__ uint32_t s2u(const void* p) {
    return (uint32_t)__cvta_generic_to_shared(p);
}
__device__ __forceinline__ void mma_tf32(float c[4],
                                         uint32_t a0, uint32_t a1, uint32_t a2, uint32_t a3,
                                         uint32_t b0, uint32_t b1) {
    asm volatile(
        "mma.sync.aligned.m16n8k8.row.col.f32.tf32.tf32.f32 "
        "{%0,%1,%2,%3},{%4,%5,%6,%7},{%8,%9},{%0,%1,%2,%3};"
        : "+f"(c[0]), "+f"(c[1]), "+f"(c[2]), "+f"(c[3])
        : "r"(a0), "r"(a1), "r"(a2), "r"(a3), "r"(b0), "r"(b1));
}

// ---------------- kernel 0: zero scratch ----------------
__global__ void zero_kernel() {
    int t = threadIdx.x;            // 512 threads
    if (t < 64) g_sv[t] = 0.f;
    else if (t < 384) g_se[t - 64] = 0.f;
    else if (t < 389) g_ecount[t - 384] = 0;
}

// ---------------- kernel 1: bucket edges by order ----------------
__global__ void scatter_kernel(const int* __restrict__ orders) {
    int e = blockIdx.x * 256 + threadIdx.x;
    if (e < NE) {
        int o = orders[e];
        int p = atomicAdd(&g_ecount[o], 1);
        g_eidx[o * NE + p] = e;
    }
}

// ---------------- kernel 2: column-sum of x_v ----------------
__global__ void vreduce_kernel(const float* __restrict__ xv) {
    __shared__ float red[256];
    int tid = threadIdx.x;
    int j = tid & 63, rg = tid >> 6;
    int base = blockIdx.x * 128;
    float a = 0.f;
#pragma unroll 8
    for (int k = 0; k < 32; k++) {
        int r = base + 4 * k + rg;
        if (r < NV) a += xv[r * DD + j];
    }
    red[tid] = a;
    __syncthreads();
    if (tid < DD) {
        float s = red[tid] + red[tid + 64] + red[tid + 128] + red[tid + 192];
        atomicAdd(&g_sv[tid], s);
    }
}

// ---------------- kernel 3: bucketed edge matvec x1_e = x_e @ W1[ord] + colsums ----------------
#define EPASS 16
__global__ void __launch_bounds__(256)
edge2_kernel(const float* __restrict__ xe, const float* __restrict__ W) {
    __shared__ float Wsh[4096];
    __shared__ float xsh[EPASS * DD];
    __shared__ float accsh[DD];
    int tid = threadIdx.x;
    int o = blockIdx.y;             // order 0..4
    int nb = gridDim.x;
    int n = g_ecount[o];

    const float4* Wp = reinterpret_cast<const float4*>(W + (size_t)(5 + o) * 4096);
#pragma unroll
    for (int i = 0; i < 4; i++)
        reinterpret_cast<float4*>(Wsh)[tid + 256 * i] = __ldg(Wp + tid + 256 * i);
    if (tid < DD) accsh[tid] = 0.f;
    __syncthreads();

    int el = tid >> 4;              // 0..15 edge slot
    int jt = tid & 15;              // 4-col group
    for (int base = blockIdx.x * EPASS; base < n; base += nb * EPASS) {
        int cnt = min(EPASS, n - base);
        float4 xr = make_float4(0.f, 0.f, 0.f, 0.f);
        int e = -1;
        if (el < cnt) {
            e = g_eidx[o * NE + base + el];
            xr = __ldg(reinterpret_cast<const float4*>(xe + (size_t)e * DD) + jt);
        }
        reinterpret_cast<float4*>(xsh)[el * 16 + jt] = xr;
        __syncthreads();

        if (tid < DD) {
            float s = 0.f;
#pragma unroll
            for (int k = 0; k < EPASS; k++) s += xsh[k * DD + tid];
            accsh[tid] += s;
        }
        if (el < cnt) {
            float4 acc = make_float4(0.f, 0.f, 0.f, 0.f);
#pragma unroll 8
            for (int i = 0; i < DD; i++) {
                float x = xsh[el * DD + i];
                float4 w = *reinterpret_cast<const float4*>(&Wsh[i * DD + jt * 4]);
                acc.x = fmaf(x, w.x, acc.x);
                acc.y = fmaf(x, w.y, acc.y);
                acc.z = fmaf(x, w.z, acc.z);
                acc.w = fmaf(x, w.w, acc.w);
            }
            reinterpret_cast<float4*>(g_x1e)[(size_t)e * 16 + jt] = acc;
        }
        __syncthreads();
    }
    if (tid < DD) atomicAdd(&g_se[o * DD + tid], accsh[tid]);
}

// ---------------- kernel 4: x0 + b (parallel: 384 threads, 6 matvecs) ----------------
__global__ void __launch_bounds__(384)
x0_kernel(const float* __restrict__ W, const float* __restrict__ b) {
    __shared__ float part[6][DD];
    int tid = threadIdx.x;
    int mat = tid / DD;             // 0..5
    int j = tid & 63;
    const float* v = (mat == 0) ? g_sv : g_se + (mat - 1) * DD;
    const float* Wm = W + (size_t)((mat == 0) ? 1 : (mat - 1)) * 4096;   // W[0][*]
    float acc = 0.f;
#pragma unroll 16
    for (int i = 0; i < DD; i++)
        acc = fmaf(v[i], __ldg(Wm + i * DD + j), acc);
    part[mat][j] = acc;
    __syncthreads();
    if (tid < DD) {
        float s = 0.f;
#pragma unroll
        for (int m = 0; m < 6; m++) s += part[m][tid];
        g_x0b[tid] = s * (1.0f / 20000.0f) + b[tid];
    }
}

// ---------------- kernel 5: split-K tf32 GEMM, coalesced cp.async A staging ----------------
__global__ void __launch_bounds__(128)
gemm_kernel(const float* __restrict__ inc) {
    __shared__ float As[2][128 * 32];   // 32 KB, XOR-swizzled 16B chunks per row
    __shared__ float Bs[2][32 * 64];    // 16 KB, XOR-swizzled per row

    int tid = threadIdx.x;
    int warp = tid >> 5, lane = tid & 31;
    int g = lane >> 2, tig = lane & 3;
    int tile = blockIdx.x, split = blockIdx.y;

    int b0 = (split * NKBLK) / NSPLIT;
    int b1 = ((split + 1) * NKBLK) / NSPLIT;
    int niter = b1 - b0;
    int kbase = b0 * BK;

    // A staging: warp-cooperative coalesced. Warp w owns rows [32w, 32w+32).
    // lane l -> row 4i + (l>>3), 16B chunk (l&7); 8 lanes cover one contiguous
    // 128B row-chunk => 4 L1 lines per LDGSTS (coalesced).
    int arbase = warp * 32 + (lane >> 3);   // + 4*i
    int achunk = lane & 7;
    uint32_t abuf[2] = { s2u(&As[0][0]), s2u(&As[1][0]) };

    int brow = tid >> 4, bc4 = tid & 15;

    float Creg[2][8][4];
#pragma unroll
    for (int m = 0; m < 2; m++)
#pragma unroll
        for (int n8 = 0; n8 < 8; n8++)
#pragma unroll
            for (int c = 0; c < 4; c++) Creg[m][n8][c] = 0.f;

#define STAGE_A(buf, kb) do {                                                  \
    _Pragma("unroll")                                                          \
    for (int i = 0; i < 8; i++) {                                              \
        int rl = arbase + i * 4;            /* 0..127 within tile */           \
        int grow = tile * 128 + rl;                                            \
        unsigned sz = (grow < NV) ? 16u : 0u;                                  \
        uint32_t d = abuf[buf] +                                               \
            (uint32_t)(rl * 128 + ((achunk ^ (rl & 7)) << 4));                 \
        const float* s = inc + (size_t)(grow < NV ? grow : 0) * NE             \
                             + (kb) + achunk * 4;                              \
        asm volatile("cp.async.ca.shared.global [%0], [%1], 16, %2;"           \
                     :: "r"(d), "l"(s), "r"(sz));                              \
    }                                                                          \
    asm volatile("cp.async.commit_group;");                                    \
} while (0)

#define LDG_B(dst, kb) do {                                                    \
    _Pragma("unroll")                                                          \
    for (int cc = 0; cc < 4; cc++)                                             \
        dst[cc] = __ldg(reinterpret_cast<const float4*>(                       \
                        g_x1e + (size_t)((kb) + brow + 8 * cc) * DD) + bc4);   \
} while (0)

#define STS_B(buf, src) do {                                                   \
    _Pragma("unroll")                                                          \
    for (int cc = 0; cc < 4; cc++) {                                           \
        int br = brow + 8 * cc;                                                \
        int pc = bc4 ^ (2 * (br & 3));                                         \
        float4 v;                                                              \
        v.x = __uint_as_float(tf32_cvt(src[cc].x));                            \
        v.y = __uint_as_float(tf32_cvt(src[cc].y));                            \
        v.z = __uint_as_float(tf32_cvt(src[cc].z));                            \
        v.w = __uint_as_float(tf32_cvt(src[cc].w));                            \
        *reinterpret_cast<float4*>(&Bs[buf][br * 64 + pc * 4]) = v;            \
    }                                                                          \
} while (0)

    // ---- prologue ----
    float4 bp[4];
    STAGE_A(0, kbase);
    LDG_B(bp, kbase);
    STS_B(0, bp);
    asm volatile("cp.async.wait_group 0;");
    __syncthreads();

    int rb0 = warp * 16 + g;
    for (int it = 0; it < niter; ++it) {
        int cbuf = it & 1, nbuf = cbuf ^ 1;
        bool hasnext = (it + 1) < niter;
        if (hasnext) {
            int kb = kbase + (it + 1) * BK;
            STAGE_A(nbuf, kb);
            LDG_B(bp, kb);
        }
        const float* Ac = As[cbuf];
        const float* Bc = Bs[cbuf];
#pragma unroll
        for (int q = 0; q < 4; q++) {
            uint32_t bf0[8], bf1[8];
            int kr = q * 8 + tig;
#pragma unroll
            for (int n8 = 0; n8 < 8; n8++) {
                int pc0 = ((n8 ^ tig) << 3) + g;
                bf0[n8] = __float_as_uint(Bc[kr * 64 + pc0]);
                bf1[n8] = __float_as_uint(Bc[(kr + 4) * 64 + pc0]);
            }
#pragma unroll
            for (int m = 0; m < 2; m++) {
                int r = rb0 + m * 64;
                int c0 = (((2 * q) ^ g) << 2) + tig;
                int c1 = (((2 * q + 1) ^ g) << 2) + tig;
                uint32_t a0 = tf32_cvt(Ac[r * 32 + c0]);
                uint32_t a1 = tf32_cvt(Ac[(r + 8) * 32 + c0]);
                uint32_t a2 = tf32_cvt(Ac[r * 32 + c1]);
                uint32_t a3 = tf32_cvt(Ac[(r + 8) * 32 + c1]);
#pragma unroll
                for (int n8 = 0; n8 < 8; n8++)
                    mma_tf32(Creg[m][n8], a0, a1, a2, a3, bf0[n8], bf1[n8]);
            }
        }
        if (hasnext) {
            STS_B(nbuf, bp);
            asm volatile("cp.async.wait_group 0;");
            __syncthreads();
        }
    }

    // ---- store split partials ----
    int rowbase = tile * 128 + warp * 16;
#pragma unroll
    for (int m = 0; m < 2; m++) {
#pragma unroll
        for (int part = 0; part < 2; part++) {
            int row = rowbase + m * 64 + part * 8 + g;
            if (row < NV) {
                float* op = g_csplit + ((size_t)split * NV + row) * DD + tig * 2;
#pragma unroll
                for (int n8 = 0; n8 < 8; n8++) {
                    float2 v2 = make_float2(Creg[m][n8][part * 2],
                                            Creg[m][n8][part * 2 + 1]);
                    *reinterpret_cast<float2*>(op + n8 * 8) = v2;
                }
            }
        }
    }
}

// ---------------- kernel 6: epilogue ----------------
__global__ void __launch_bounds__(256)
epilogue_kernel(const float* __restrict__ xv,
                const float* __restrict__ sn,
                const float* __restrict__ W,
                float* __restrict__ out) {
    __shared__ float Wsh[DD * DD];
    __shared__ float xvsh[4 * DD];
    int tid = threadIdx.x;
    int r0 = blockIdx.x * 4;
    int rloc = tid >> 6, j = tid & 63;
    int row = r0 + rloc;

    const float4* W4 = reinterpret_cast<const float4*>(W + 6 * 4096);  // W[1][1]
#pragma unroll
    for (int c = 0; c < 4; c++)
        reinterpret_cast<float4*>(Wsh)[tid + 256 * c] = __ldg(W4 + tid + 256 * c);
    if (tid < 64)
        reinterpret_cast<float4*>(xvsh)[tid] =
            __ldg(reinterpret_cast<const float4*>(xv + (size_t)r0 * DD) + tid);
    __syncthreads();

    float acc = 0.f;
#pragma unroll 8
    for (int i = 0; i < DD; i++)
        acc = fmaf(xvsh[rloc * DD + i], Wsh[i * DD + j], acc);

    float csum = 0.f;
#pragma unroll
    for (int s = 0; s < NSPLIT; s++)
        csum += g_csplit[((size_t)s * NV + row) * DD + j];

    float rinv = 1.0f / (1.0f + __ldg(sn + row));
    out[(size_t)row * DD + j] = (acc + csum) * rinv + g_x0b[j];
}

// ---------------- launch ----------------
extern "C" void kernel_launch(void* const* d_in, const int* in_sizes, int n_in,
                              void* d_out, int out_size) {
    const float* x_v    = (const float*)d_in[0];
    const float* x_e    = (const float*)d_in[1];
    const float* inc    = (const float*)d_in[2];
    const int*   orders = (const int*)  d_in[3];
    const float* sn     = (const float*)d_in[4];
    const float* W      = (const float*)d_in[5];
    const float* b      = (const float*)d_in[6];
    float*       out    = (float*)d_out;

    zero_kernel    <<<1, 512>>>();
    scatter_kernel <<<(NE + 255) / 256, 256>>>(orders);
    vreduce_kernel <<<32, 256>>>(x_v);
    dim3 egrid(200, 5);
    edge2_kernel   <<<egrid, 256>>>(x_e, W);
    x0_kernel      <<<1, 384>>>(W, b);
    dim3 ggrid(32, NSPLIT);
    gemm_kernel    <<<ggrid, 128>>>(inc);
    epilogue_kernel<<<NV / 4, 256>>>(x_v, sn, W, out);
}